// round 15
// baseline (speedup 1.0000x reference)
#include <cuda_runtime.h>
#include <cstdint>

#define Bn 8
#define Fn 64
#define Dn 20
#define FSn 160
#define Tn (Fn*FSn)   // 10240
#define CL 8

// ---------------- scratch (device globals; no allocation) ----------------
__device__ float g_c1[Bn*Fn*128];
__device__ float g_c2[Bn*Fn*128];
__device__ float g_cond[Bn*Fn*128];

// ---------------- helpers ----------------
__device__ __forceinline__ uint32_t cl_rank(){
    uint32_t r; asm("mov.u32 %0, %%cluster_ctarank;" : "=r"(r)); return r;
}
__device__ __forceinline__ uint32_t sm2u(const void* p){
    return (uint32_t)__cvta_generic_to_shared(p);
}
__device__ __forceinline__ uint32_t mapa_u32(uint32_t a, uint32_t rnk){
    uint32_t d;
    asm("mapa.shared::cluster.u32 %0, %1, %2;" : "=r"(d) : "r"(a), "r"(rnk));
    return d;
}
__device__ __forceinline__ void cl_arrive(){ asm volatile("barrier.cluster.arrive.aligned;" ::: "memory"); }
__device__ __forceinline__ void cl_wait(){ asm volatile("barrier.cluster.wait.aligned;" ::: "memory"); }

__device__ __forceinline__ void mbar_init(uint32_t mbar, uint32_t cnt){
    asm volatile("mbarrier.init.shared.b64 [%0], %1;" :: "r"(mbar), "r"(cnt) : "memory");
}
__device__ __forceinline__ void mbar_arrive_expect(uint32_t mbar, uint32_t bytes){
    asm volatile("mbarrier.arrive.expect_tx.shared.b64 _, [%0], %1;" :: "r"(mbar), "r"(bytes) : "memory");
}
__device__ __forceinline__ void mbar_wait(uint32_t mbar, uint32_t parity){
    uint32_t done;
    do {
        asm volatile(
            "{\n\t.reg .pred p;\n\t"
            "mbarrier.try_wait.parity.acquire.cta.shared::cta.b64 p, [%1], %2, 0x989680;\n\t"
            "selp.b32 %0, 1, 0, p;\n\t}"
            : "=r"(done) : "r"(mbar), "r"(parity) : "memory");
    } while (!done);
}
// one-sided stores with PRE-MAPPED remote addresses (mapa hoisted out of loop)
__device__ __forceinline__ void st_async_v4_pre(uint32_t rd, uint32_t rm,
                                                float a, float b2, float c, float d){
    asm volatile("st.async.weak.shared::cluster.mbarrier::complete_tx::bytes.v4.b32 "
                 "[%0], {%1,%2,%3,%4}, [%5];"
                 :: "r"(rd), "r"(__float_as_uint(a)), "r"(__float_as_uint(b2)),
                    "r"(__float_as_uint(c)), "r"(__float_as_uint(d)), "r"(rm) : "memory");
}
__device__ __forceinline__ void st_async_u64_pre(uint32_t rd, uint32_t rm, unsigned long long v){
    asm volatile("st.async.weak.shared::cluster.mbarrier::complete_tx::bytes.b64 [%0], %1, [%2];"
                 :: "r"(rd), "l"(v), "r"(rm) : "memory");
}

__device__ __forceinline__ float tanh_approx(float x){
    float y; asm("tanh.approx.f32 %0, %1;" : "=f"(y) : "f"(x)); return y;
}
__device__ __forceinline__ float fsigm_fast(float x){   // sigma(x)=0.5*tanh(x/2)+0.5
    return fmaf(tanh_approx(0.5f*x), 0.5f, 0.5f);
}
// monotone float->uint map (larger float => larger uint), finite inputs
__device__ __forceinline__ uint32_t ford(float f){
    uint32_t u = __float_as_uint(f);
    return (u & 0x80000000u) ? ~u : (u | 0x80000000u);
}

// ---------------- FrameRateNet (tiny, 3 kernels) ----------------
__global__ void frn_conv1(const float* __restrict__ feat,
                          const float* __restrict__ w,
                          const float* __restrict__ bias){
    int bf = blockIdx.x; int b = bf >> 6, f = bf & 63;
    int o = threadIdx.x;
    float acc = bias[o];
#pragma unroll
    for (int k = 0; k < 3; k++){
        int ff = f + k - 1;
        if (ff < 0 || ff >= Fn) continue;
        const float* fr = feat + (b*Fn + ff)*Dn;
#pragma unroll
        for (int i = 0; i < Dn; i++) acc += fr[i]*w[(k*Dn + i)*128 + o];
    }
    g_c1[bf*128 + o] = tanhf(acc);
}

__global__ void frn_conv2(const float* __restrict__ w,
                          const float* __restrict__ bias){
    __shared__ float srow[3*128];
    int bf = blockIdx.x; int b = bf >> 6, f = bf & 63;
    int o = threadIdx.x;
#pragma unroll
    for (int k = 0; k < 3; k++){
        int ff = f + k - 1;
        srow[k*128 + o] = (ff >= 0 && ff < Fn) ? g_c1[(b*Fn + ff)*128 + o] : 0.f;
    }
    __syncthreads();
    float acc = bias[o];
#pragma unroll 1
    for (int k = 0; k < 3; k++)
        for (int i = 0; i < 128; i++)
            acc += srow[k*128 + i]*w[(k*128 + i)*128 + o];
    g_c2[bf*128 + o] = tanhf(acc);
}

__global__ void frn_fc(const float* __restrict__ w1, const float* __restrict__ b1,
                       const float* __restrict__ w2, const float* __restrict__ b2){
    __shared__ float sv[128], sm_[128];
    int bf = blockIdx.x; int o = threadIdx.x;
    sv[o] = g_c2[bf*128 + o];
    __syncthreads();
    float a = b1[o];
    for (int j = 0; j < 128; j++) a += sv[j]*w1[j*128 + o];
    sm_[o] = tanhf(a);
    __syncthreads();
    float c = b2[o];
    for (int i = 0; i < 128; i++) c += sm_[i]*w2[i*128 + o];
    g_cond[bf*128 + o] = tanhf(c);
}

// ---------------- persistent autoregressive GRU ----------------
// 64 CTAs, clusters of 8 (one per batch). CTA rank c owns hidden units and
// logit columns [32c,32c+32). 256 threads = 32 groups (jl) x 8 stripes (s).
// EXACT R12 topology (best measured): owner/argmax on warp 0; mbarrier armers
// tid 0/32/64, each arming the barrier its OWN warp waits on. Only delta vs
// R12: n-gate uses tanh.approx (validated rel_err 2.9e-6 in R13/R14).
__global__ void __launch_bounds__(256, 1) __cluster_dims__(CL, 1, 1)
gru_kernel(const float* __restrict__ wi_g, const float* __restrict__ wh_g,
           const float* __restrict__ bi_g, const float* __restrict__ bh_g,
           const float* __restrict__ ow_g, const float* __restrict__ ob_g,
           float* __restrict__ wav_out, float* __restrict__ logits_out)
{
    __shared__ __align__(16) float sh_h[2][256];      // double-buffered hidden state
    __shared__ __align__(16) float sh_P[2][CL][32];   // partial-logit slices [buf][src][col]
    __shared__ __align__(16) unsigned long long sh_enc[2][CL];  // per-src-CTA best enc
    __shared__ float sh_cond[128];                    // current-frame conditioning
    __shared__ float sh_mu[256];                      // mu-law idx -> sample LUT
    __shared__ __align__(8) unsigned long long sh_mb[6];  // H0,H1,P0,P1,E0,E1

    const int tid  = threadIdx.x;
    const int rank = (int)cl_rank();
    const int b    = blockIdx.x / CL;
    const int lane = tid & 31;
    const int wid  = tid >> 5;
    const int jl   = wid*4 + (lane >> 3);         // local unit 0..31
    const int s    = lane & 7;                    // k-stripe 0..7
    const int u    = rank*32 + jl;                // global hidden unit

    // ---- recurrent weights into registers ----
    float whr[32], whz[32], whn[32];
#pragma unroll
    for (int m = 0; m < 32; m++){
        int k = s + 8*m;
        whr[m] = wh_g[(u      )*256 + k];
        whz[m] = wh_g[(256 + u)*256 + k];
        whn[m] = wh_g[(512 + u)*256 + k];
    }
    const float wpr = wi_g[(u      )*129];
    const float wpz = wi_g[(256 + u)*129];
    const float wpn = wi_g[(512 + u)*129];
    float wcr[16], wcz[16], wcn[16];
#pragma unroll
    for (int m = 0; m < 16; m++){
        int k = 1 + s + 8*m;
        wcr[m] = wi_g[(u      )*129 + k];
        wcz[m] = wi_g[(256 + u)*129 + k];
        wcn[m] = wi_g[(512 + u)*129 + k];
    }
    // output weights: thread covers its CTA's 32 h-rows for logit column tid
    float ow[32];
#pragma unroll
    for (int j2 = 0; j2 < 32; j2++) ow[j2] = ow_g[(rank*32 + j2)*256 + tid];
    const float ob   = (tid < 32) ? ob_g[rank*32 + tid] : 0.f;
    const float bsr  = bi_g[u]       + bh_g[u];
    const float bsz  = bi_g[256 + u] + bh_g[256 + u];
    const float bin_ = bi_g[512 + u];
    const float bhn  = bh_g[512 + u];

    // ---- init shared state + mbarriers + mu-law LUT ----
    for (int i = tid; i < 2*256; i += 256) ((float*)sh_h)[i] = 0.f;
    if (tid < 128) sh_cond[tid] = g_cond[(b*Fn + 0)*128 + tid];
    if (tid < 6) mbar_init(sm2u(&sh_mb[tid]), 1);
    {
        float v  = ((float)tid + 0.5f)*(1.f/128.f) - 1.f;
        float av = fabsf(v);
        sh_mu[tid] = copysignf((exp2f(8.f*av) - 1.f)*(1.f/255.f), v);
    }
    __syncthreads();

    float cr, cz, cn;
    auto calc_consts = [&](){
        float tr = 0.f, tz = 0.f, tn2 = 0.f;
#pragma unroll
        for (int m = 0; m < 16; m++){
            float cv = sh_cond[s + 8*m];
            tr  = fmaf(wcr[m], cv, tr);
            tz  = fmaf(wcz[m], cv, tz);
            tn2 = fmaf(wcn[m], cv, tn2);
        }
#pragma unroll
        for (int off = 4; off >= 1; off >>= 1){
            tr  += __shfl_xor_sync(0xffffffffu, tr,  off);
            tz  += __shfl_xor_sync(0xffffffffu, tz,  off);
            tn2 += __shfl_xor_sync(0xffffffffu, tn2, off);
        }
        cr = tr + bsr; cz = tz + bsz; cn = tn2 + bin_;
    };
    calc_consts();

    cl_arrive(); cl_wait();   // one-time: peers' smem + mbarriers initialized

    const uint32_t mbH[2] = { sm2u(&sh_mb[0]), sm2u(&sh_mb[1]) };
    const uint32_t mbP[2] = { sm2u(&sh_mb[2]), sm2u(&sh_mb[3]) };
    const uint32_t mbE[2] = { sm2u(&sh_mb[4]), sm2u(&sh_mb[5]) };

    // ---- pre-mapped remote addresses (mapa hoisted out of the loop) ----
    uint32_t h_rd[2], h_rm[2], p_rd[2], p_rm[2], e_rd[2], e_rm[2];
#pragma unroll
    for (int q = 0; q < 2; q++){
        uint32_t dl = (uint32_t)(lane & 7);
        h_rd[q] = mapa_u32(sm2u(&sh_h[q][rank*32 + wid*4]), dl);
        h_rm[q] = mapa_u32(mbH[q], dl);
        p_rd[q] = mapa_u32(sm2u(&sh_P[q][rank][lane & ~3]), (uint32_t)wid);
        p_rm[q] = mapa_u32(mbP[q], (uint32_t)wid);
        e_rd[q] = mapa_u32(sm2u(&sh_enc[q][rank]), dl);
        e_rm[q] = mapa_u32(mbE[q], dl);
    }

    float prev = 0.f, hold = 0.f, y = 0.f;
    float ghr = 0.f, ghz = 0.f, ghn = 0.f;   // pipelined, REDUCED W_hh.h partials (h(-1)=0)

    for (int t = 0; t < Tn; ++t){
        const int bq = t & 1;
        const uint32_t pc = (uint32_t)((t >> 1) & 1);

        // arm mbarriers; each armer is in a warp that WAITS that barrier
        if (tid == 0)       mbar_arrive_expect(mbP[bq], 8*8*16);   // pv: 8 srcs x 8 v4
        else if (tid == 32) mbar_arrive_expect(mbH[bq], 7*8*16);   // h: 7 remote x 8 v4
        else if (tid == 64) mbar_arrive_expect(mbE[bq], CL*8);     // enc: 8 x u64

        // ---------- gates tail: W_hh partials were precomputed last step ----------
        float rg   = fsigm_fast(ghr + cr + wpr*prev);
        float zg   = fsigm_fast(ghz + cz + wpz*prev);
        float ng   = tanh_approx(cn + wpn*prev + rg*(ghn + bhn));
        float hnew = fmaf(zg, hold - ng, ng);     // (1-z)n + z*hold
        hold = hnew;

        // gather this warp's 4 unit values into lanes 0..7 (one per dest CTA)
        float v1 = __shfl_sync(0xffffffffu, hnew, (lane & 7) + 8);
        float v2 = __shfl_sync(0xffffffffu, hnew, (lane & 7) + 16);
        float v3 = __shfl_sync(0xffffffffu, hnew, (lane & 7) + 24);
        if (lane == rank)   // local copy of this warp's slice
            *reinterpret_cast<float4*>(&sh_h[bq][rank*32 + wid*4]) =
                make_float4(hnew, v1, v2, v3);
        __syncthreads();    // local slice complete; anti-WAR before sends
        if (lane < 8 && lane != rank)
            st_async_v4_pre(h_rd[bq], h_rm[bq], hnew, v1, v2, v3);

        // partial logits from LOCAL h slice (2 accumulators)
        float pv0 = 0.f, pv1 = 0.f;
        {
            const float* hq = sh_h[bq] + rank*32;
#pragma unroll
            for (int j2 = 0; j2 < 16; j2++){
                pv0 = fmaf(hq[j2],      ow[j2],      pv0);
                pv1 = fmaf(hq[j2 + 16], ow[j2 + 16], pv1);
            }
        }
        float pv = pv0 + pv1;
        // gather 4 columns into lanes 0 mod 4, one v4 per group to owner CTA
        float q1 = __shfl_sync(0xffffffffu, pv, (lane & ~3) + 1);
        float q2 = __shfl_sync(0xffffffffu, pv, (lane & ~3) + 2);
        float q3 = __shfl_sync(0xffffffffu, pv, (lane & ~3) + 3);
        if ((lane & 3) == 0)
            st_async_v4_pre(p_rd[bq], p_rm[bq], pv, q1, q2, q3);

        int tn1 = t + 1;
        bool boundary = (tn1 < Tn) && ((tn1 % FSn) == 0);

        // ---------- warp 0 ONLY: final logits + argmax + E broadcast ----------
        if (wid == 0){
            mbar_wait(mbP[bq], pc);
            const float* Pp = &sh_P[bq][0][lane];
            float l0 = ob, l1 = 0.f;
#pragma unroll
            for (int src = 0; src < CL; src += 2){
                l0 += Pp[(src    )*32];
                l1 += Pp[(src + 1)*32];
            }
            float logit = l0 + l1;
            uint32_t fo = ford(logit);
            uint32_t mvu = __reduce_max_sync(0xffffffffu, fo);
            uint32_t mask = __ballot_sync(0xffffffffu, fo == mvu);
            int mi = rank*32 + (__ffs(mask) - 1);                  // lowest index on ties
            unsigned long long enc = ((unsigned long long)mvu << 8)
                                   | (unsigned long long)(255 - mi);
            if (lane < CL)   // parallel 8-way broadcast, one dest per lane
                st_async_u64_pre(e_rd[bq], e_rm[bq], enc);
            // overlap the logits STG with the enc flight
            logits_out[((size_t)(b*Tn + t))*256 + rank*32 + lane] = logit;
        }

        // per-frame cond reload (write half) overlaps the flights
        if (boundary && tid < 128) sh_cond[tid] = g_cond[(b*Fn + tn1/FSn)*128 + tid];

        // ---------- all warps: next step's W_hh.h(t) during the flights ----------
        mbar_wait(mbH[bq], pc);        // full h(t); early for warps 1-7
        {
            const float* hp = sh_h[bq];
            float a0 = 0.f, a1 = 0.f, a2 = 0.f;
#pragma unroll
            for (int m = 0; m < 32; m++){
                float hv = hp[s + 8*m];            // conflict-free broadcast LDS
                a0 = fmaf(whr[m], hv, a0);
                a1 = fmaf(whz[m], hv, a1);
                a2 = fmaf(whn[m], hv, a2);
            }
#pragma unroll
            for (int off = 4; off >= 1; off >>= 1){
                a0 += __shfl_xor_sync(0xffffffffu, a0, off);
                a1 += __shfl_xor_sync(0xffffffffu, a1, off);
                a2 += __shfl_xor_sync(0xffffffffu, a2, off);
            }
            ghr = a0; ghz = a1; ghn = a2;
        }

        // ---------- global argmax combine, LUT sample, de-emphasis ----------
        mbar_wait(mbE[bq], pc);
        {
            const ulonglong2* ep = reinterpret_cast<const ulonglong2*>(&sh_enc[bq][0]);
            ulonglong2 e0 = ep[0], e1 = ep[1], e2 = ep[2], e3 = ep[3];
            unsigned long long m0 = (e0.x > e0.y) ? e0.x : e0.y;
            unsigned long long m1 = (e1.x > e1.y) ? e1.x : e1.y;
            unsigned long long m2 = (e2.x > e2.y) ? e2.x : e2.y;
            unsigned long long m3 = (e3.x > e3.y) ? e3.x : e3.y;
            m0 = (m1 > m0) ? m1 : m0;
            m2 = (m3 > m2) ? m3 : m2;
            unsigned long long best = (m2 > m0) ? m2 : m0;
            int idx = 255 - (int)(best & 0xFFull);
            prev = sh_mu[idx];
        }
        if (rank == 0 && tid == 0){
            y = prev + 0.97f*y;
            wav_out[b*Tn + t] = y;
        }
        if (boundary){
            __syncthreads();      // cond writes visible before recompute
            calc_consts();
        }
    }
}

// ---------------- launch ----------------
extern "C" void kernel_launch(void* const* d_in, const int* in_sizes, int n_in,
                              void* d_out, int out_size)
{
    const float* features = (const float*)d_in[0];
    const float* c1w = (const float*)d_in[1];
    const float* c1b = (const float*)d_in[2];
    const float* c2w = (const float*)d_in[3];
    const float* c2b = (const float*)d_in[4];
    const float* f1w = (const float*)d_in[5];
    const float* f1b = (const float*)d_in[6];
    const float* f2w = (const float*)d_in[7];
    const float* f2b = (const float*)d_in[8];
    const float* wi  = (const float*)d_in[9];
    const float* wh  = (const float*)d_in[10];
    const float* bi  = (const float*)d_in[11];
    const float* bh  = (const float*)d_in[12];
    const float* oww = (const float*)d_in[13];
    const float* obb = (const float*)d_in[14];

    float* out    = (float*)d_out;
    float* wav    = out;                       // (B, T, 1) flattened first
    float* logits = out + (size_t)Bn*Tn;       // (B, T, 256) after

    frn_conv1<<<Bn*Fn, 128>>>(features, c1w, c1b);
    frn_conv2<<<Bn*Fn, 128>>>(c2w, c2b);
    frn_fc   <<<Bn*Fn, 128>>>(f1w, f1b, f2w, f2b);
    gru_kernel<<<Bn*CL, 256>>>(wi, wh, bi, bh, oww, obb, wav, logits);
}

// round 16
// speedup vs baseline: 1.5295x; 1.5295x over previous
#include <cuda_runtime.h>
#include <cstdint>

#define Bn 8
#define Fn 64
#define Dn 20
#define FSn 160
#define Tn (Fn*FSn)   // 10240
#define CL 8

// ---------------- scratch (device globals; no allocation) ----------------
__device__ float g_c1[Bn*Fn*128];
__device__ float g_c2[Bn*Fn*128];
__device__ float g_cond[Bn*Fn*128];

// ---------------- helpers ----------------
__device__ __forceinline__ uint32_t cl_rank(){
    uint32_t r; asm("mov.u32 %0, %%cluster_ctarank;" : "=r"(r)); return r;
}
__device__ __forceinline__ uint32_t sm2u(const void* p){
    return (uint32_t)__cvta_generic_to_shared(p);
}
__device__ __forceinline__ uint32_t mapa_u32(uint32_t a, uint32_t rnk){
    uint32_t d;
    asm("mapa.shared::cluster.u32 %0, %1, %2;" : "=r"(d) : "r"(a), "r"(rnk));
    return d;
}
__device__ __forceinline__ void cl_arrive(){ asm volatile("barrier.cluster.arrive.aligned;" ::: "memory"); }
__device__ __forceinline__ void cl_wait(){ asm volatile("barrier.cluster.wait.aligned;" ::: "memory"); }

__device__ __forceinline__ void mbar_init(uint32_t mbar, uint32_t cnt){
    asm volatile("mbarrier.init.shared.b64 [%0], %1;" :: "r"(mbar), "r"(cnt) : "memory");
}
__device__ __forceinline__ void mbar_arrive_expect(uint32_t mbar, uint32_t bytes){
    asm volatile("mbarrier.arrive.expect_tx.shared.b64 _, [%0], %1;" :: "r"(mbar), "r"(bytes) : "memory");
}
__device__ __forceinline__ void mbar_wait(uint32_t mbar, uint32_t parity){
    uint32_t done;
    do {
        asm volatile(
            "{\n\t.reg .pred p;\n\t"
            "mbarrier.try_wait.parity.acquire.cta.shared::cta.b64 p, [%1], %2, 0x989680;\n\t"
            "selp.b32 %0, 1, 0, p;\n\t}"
            : "=r"(done) : "r"(mbar), "r"(parity) : "memory");
    } while (!done);
}
// one-sided stores with PRE-MAPPED remote addresses (mapa hoisted out of loop)
__device__ __forceinline__ void st_async_v4_pre(uint32_t rd, uint32_t rm,
                                                float a, float b2, float c, float d){
    asm volatile("st.async.weak.shared::cluster.mbarrier::complete_tx::bytes.v4.b32 "
                 "[%0], {%1,%2,%3,%4}, [%5];"
                 :: "r"(rd), "r"(__float_as_uint(a)), "r"(__float_as_uint(b2)),
                    "r"(__float_as_uint(c)), "r"(__float_as_uint(d)), "r"(rm) : "memory");
}
__device__ __forceinline__ void st_async_u64_pre(uint32_t rd, uint32_t rm, unsigned long long v){
    asm volatile("st.async.weak.shared::cluster.mbarrier::complete_tx::bytes.b64 [%0], %1, [%2];"
                 :: "r"(rd), "l"(v), "r"(rm) : "memory");
}

__device__ __forceinline__ float tanh_approx(float x){
    float y; asm("tanh.approx.f32 %0, %1;" : "=f"(y) : "f"(x)); return y;
}
__device__ __forceinline__ float fsigm_fast(float x){   // sigma(x)=0.5*tanh(x/2)+0.5
    return fmaf(tanh_approx(0.5f*x), 0.5f, 0.5f);
}
__device__ __forceinline__ float ftanh(float x){        // accurate (n-gate)
    x = fminf(fmaxf(x, -10.f), 10.f);
    float e = __expf(2.f*x);
    return (e - 1.f)/(e + 1.f);
}
// monotone float->uint map (larger float => larger uint), finite inputs
__device__ __forceinline__ uint32_t ford(float f){
    uint32_t u = __float_as_uint(f);
    return (u & 0x80000000u) ? ~u : (u | 0x80000000u);
}

// ---------------- FrameRateNet (tiny, 3 kernels) ----------------
__global__ void frn_conv1(const float* __restrict__ feat,
                          const float* __restrict__ w,
                          const float* __restrict__ bias){
    int bf = blockIdx.x; int b = bf >> 6, f = bf & 63;
    int o = threadIdx.x;
    float acc = bias[o];
#pragma unroll
    for (int k = 0; k < 3; k++){
        int ff = f + k - 1;
        if (ff < 0 || ff >= Fn) continue;
        const float* fr = feat + (b*Fn + ff)*Dn;
#pragma unroll
        for (int i = 0; i < Dn; i++) acc += fr[i]*w[(k*Dn + i)*128 + o];
    }
    g_c1[bf*128 + o] = tanhf(acc);
}

__global__ void frn_conv2(const float* __restrict__ w,
                          const float* __restrict__ bias){
    __shared__ float srow[3*128];
    int bf = blockIdx.x; int b = bf >> 6, f = bf & 63;
    int o = threadIdx.x;
#pragma unroll
    for (int k = 0; k < 3; k++){
        int ff = f + k - 1;
        srow[k*128 + o] = (ff >= 0 && ff < Fn) ? g_c1[(b*Fn + ff)*128 + o] : 0.f;
    }
    __syncthreads();
    float acc = bias[o];
#pragma unroll 1
    for (int k = 0; k < 3; k++)
        for (int i = 0; i < 128; i++)
            acc += srow[k*128 + i]*w[(k*128 + i)*128 + o];
    g_c2[bf*128 + o] = tanhf(acc);
}

__global__ void frn_fc(const float* __restrict__ w1, const float* __restrict__ b1,
                       const float* __restrict__ w2, const float* __restrict__ b2){
    __shared__ float sv[128], sm_[128];
    int bf = blockIdx.x; int o = threadIdx.x;
    sv[o] = g_c2[bf*128 + o];
    __syncthreads();
    float a = b1[o];
    for (int j = 0; j < 128; j++) a += sv[j]*w1[j*128 + o];
    sm_[o] = tanhf(a);
    __syncthreads();
    float c = b2[o];
    for (int i = 0; i < 128; i++) c += sm_[i]*w2[i*128 + o];
    g_cond[bf*128 + o] = tanhf(c);
}

// ---------------- persistent autoregressive GRU ----------------
// EXACT R12 kernel (best measured: 10.53 ms). Controlled re-bench to separate
// environment/clock drift from code effects after R14/R15 anomalies.
// 64 CTAs, clusters of 8 (one per batch). CTA rank c owns hidden units and
// logit columns [32c,32c+32). 256 threads = 32 groups (jl) x 8 stripes (s).
__global__ void __launch_bounds__(256, 1) __cluster_dims__(CL, 1, 1)
gru_kernel(const float* __restrict__ wi_g, const float* __restrict__ wh_g,
           const float* __restrict__ bi_g, const float* __restrict__ bh_g,
           const float* __restrict__ ow_g, const float* __restrict__ ob_g,
           float* __restrict__ wav_out, float* __restrict__ logits_out)
{
    __shared__ __align__(16) float sh_h[2][256];      // double-buffered hidden state
    __shared__ __align__(16) float sh_P[2][CL][32];   // partial-logit slices [buf][src][col]
    __shared__ __align__(16) unsigned long long sh_enc[2][CL];  // per-src-CTA best enc
    __shared__ float sh_cond[128];                    // current-frame conditioning
    __shared__ float sh_mu[256];                      // mu-law idx -> sample LUT
    __shared__ __align__(8) unsigned long long sh_mb[6];  // H0,H1,P0,P1,E0,E1

    const int tid  = threadIdx.x;
    const int rank = (int)cl_rank();
    const int b    = blockIdx.x / CL;
    const int lane = tid & 31;
    const int wid  = tid >> 5;
    const int jl   = wid*4 + (lane >> 3);         // local unit 0..31
    const int s    = lane & 7;                    // k-stripe 0..7
    const int u    = rank*32 + jl;                // global hidden unit

    // ---- recurrent weights into registers ----
    float whr[32], whz[32], whn[32];
#pragma unroll
    for (int m = 0; m < 32; m++){
        int k = s + 8*m;
        whr[m] = wh_g[(u      )*256 + k];
        whz[m] = wh_g[(256 + u)*256 + k];
        whn[m] = wh_g[(512 + u)*256 + k];
    }
    const float wpr = wi_g[(u      )*129];
    const float wpz = wi_g[(256 + u)*129];
    const float wpn = wi_g[(512 + u)*129];
    float wcr[16], wcz[16], wcn[16];
#pragma unroll
    for (int m = 0; m < 16; m++){
        int k = 1 + s + 8*m;
        wcr[m] = wi_g[(u      )*129 + k];
        wcz[m] = wi_g[(256 + u)*129 + k];
        wcn[m] = wi_g[(512 + u)*129 + k];
    }
    // output weights: thread covers its CTA's 32 h-rows for logit column tid
    float ow[32];
#pragma unroll
    for (int j2 = 0; j2 < 32; j2++) ow[j2] = ow_g[(rank*32 + j2)*256 + tid];
    const float ob   = (tid < 32) ? ob_g[rank*32 + tid] : 0.f;
    const float bsr  = bi_g[u]       + bh_g[u];
    const float bsz  = bi_g[256 + u] + bh_g[256 + u];
    const float bin_ = bi_g[512 + u];
    const float bhn  = bh_g[512 + u];

    // ---- init shared state + mbarriers + mu-law LUT ----
    for (int i = tid; i < 2*256; i += 256) ((float*)sh_h)[i] = 0.f;
    if (tid < 128) sh_cond[tid] = g_cond[(b*Fn + 0)*128 + tid];
    if (tid < 6) mbar_init(sm2u(&sh_mb[tid]), 1);
    {
        float v  = ((float)tid + 0.5f)*(1.f/128.f) - 1.f;
        float av = fabsf(v);
        sh_mu[tid] = copysignf((exp2f(8.f*av) - 1.f)*(1.f/255.f), v);
    }
    __syncthreads();

    float cr, cz, cn;
    auto calc_consts = [&](){
        float tr = 0.f, tz = 0.f, tn2 = 0.f;
#pragma unroll
        for (int m = 0; m < 16; m++){
            float cv = sh_cond[s + 8*m];
            tr  = fmaf(wcr[m], cv, tr);
            tz  = fmaf(wcz[m], cv, tz);
            tn2 = fmaf(wcn[m], cv, tn2);
        }
#pragma unroll
        for (int off = 4; off >= 1; off >>= 1){
            tr  += __shfl_xor_sync(0xffffffffu, tr,  off);
            tz  += __shfl_xor_sync(0xffffffffu, tz,  off);
            tn2 += __shfl_xor_sync(0xffffffffu, tn2, off);
        }
        cr = tr + bsr; cz = tz + bsz; cn = tn2 + bin_;
    };
    calc_consts();

    cl_arrive(); cl_wait();   // one-time: peers' smem + mbarriers initialized

    const uint32_t mbH[2] = { sm2u(&sh_mb[0]), sm2u(&sh_mb[1]) };
    const uint32_t mbP[2] = { sm2u(&sh_mb[2]), sm2u(&sh_mb[3]) };
    const uint32_t mbE[2] = { sm2u(&sh_mb[4]), sm2u(&sh_mb[5]) };

    // ---- pre-mapped remote addresses (mapa hoisted out of the loop) ----
    uint32_t h_rd[2], h_rm[2], p_rd[2], p_rm[2], e_rd[2], e_rm[2];
#pragma unroll
    for (int q = 0; q < 2; q++){
        uint32_t dl = (uint32_t)(lane & 7);
        h_rd[q] = mapa_u32(sm2u(&sh_h[q][rank*32 + wid*4]), dl);
        h_rm[q] = mapa_u32(mbH[q], dl);
        p_rd[q] = mapa_u32(sm2u(&sh_P[q][rank][lane & ~3]), (uint32_t)wid);
        p_rm[q] = mapa_u32(mbP[q], (uint32_t)wid);
        e_rd[q] = mapa_u32(sm2u(&sh_enc[q][rank]), dl);
        e_rm[q] = mapa_u32(mbE[q], dl);
    }

    float prev = 0.f, hold = 0.f, y = 0.f;
    float ghr = 0.f, ghz = 0.f, ghn = 0.f;   // pipelined, REDUCED W_hh.h partials (h(-1)=0)

    for (int t = 0; t < Tn; ++t){
        const int bq = t & 1;
        const uint32_t pc = (uint32_t)((t >> 1) & 1);

        // arm mbarriers; each armer is in a warp that WAITS that barrier
        if (tid == 0)       mbar_arrive_expect(mbP[bq], 8*8*16);   // pv: 8 srcs x 8 v4
        else if (tid == 32) mbar_arrive_expect(mbH[bq], 7*8*16);   // h: 7 remote x 8 v4
        else if (tid == 64) mbar_arrive_expect(mbE[bq], CL*8);     // enc: 8 x u64

        // ---------- gates tail: W_hh partials were precomputed last step ----------
        float rg   = fsigm_fast(ghr + cr + wpr*prev);
        float zg   = fsigm_fast(ghz + cz + wpz*prev);
        float ng   = ftanh(cn + wpn*prev + rg*(ghn + bhn));
        float hnew = fmaf(zg, hold - ng, ng);     // (1-z)n + z*hold
        hold = hnew;

        // gather this warp's 4 unit values into lanes 0..7 (one per dest CTA)
        float v1 = __shfl_sync(0xffffffffu, hnew, (lane & 7) + 8);
        float v2 = __shfl_sync(0xffffffffu, hnew, (lane & 7) + 16);
        float v3 = __shfl_sync(0xffffffffu, hnew, (lane & 7) + 24);
        if (lane == rank)   // local copy of this warp's slice
            *reinterpret_cast<float4*>(&sh_h[bq][rank*32 + wid*4]) =
                make_float4(hnew, v1, v2, v3);
        __syncthreads();    // local slice complete; anti-WAR before sends
        if (lane < 8 && lane != rank)
            st_async_v4_pre(h_rd[bq], h_rm[bq], hnew, v1, v2, v3);

        // partial logits from LOCAL h slice (2 accumulators)
        float pv0 = 0.f, pv1 = 0.f;
        {
            const float* hq = sh_h[bq] + rank*32;
#pragma unroll
            for (int j2 = 0; j2 < 16; j2++){
                pv0 = fmaf(hq[j2],      ow[j2],      pv0);
                pv1 = fmaf(hq[j2 + 16], ow[j2 + 16], pv1);
            }
        }
        float pv = pv0 + pv1;
        // gather 4 columns into lanes 0 mod 4, one v4 per group to owner CTA
        float q1 = __shfl_sync(0xffffffffu, pv, (lane & ~3) + 1);
        float q2 = __shfl_sync(0xffffffffu, pv, (lane & ~3) + 2);
        float q3 = __shfl_sync(0xffffffffu, pv, (lane & ~3) + 3);
        if ((lane & 3) == 0)
            st_async_v4_pre(p_rd[bq], p_rm[bq], pv, q1, q2, q3);

        int tn1 = t + 1;
        bool boundary = (tn1 < Tn) && ((tn1 % FSn) == 0);

        // ---------- warp 0 ONLY: final logits + argmax + E broadcast ----------
        if (wid == 0){
            mbar_wait(mbP[bq], pc);
            const float* Pp = &sh_P[bq][0][lane];
            float l0 = ob, l1 = 0.f;
#pragma unroll
            for (int src = 0; src < CL; src += 2){
                l0 += Pp[(src    )*32];
                l1 += Pp[(src + 1)*32];
            }
            float logit = l0 + l1;
            uint32_t fo = ford(logit);
            uint32_t mvu = __reduce_max_sync(0xffffffffu, fo);
            uint32_t mask = __ballot_sync(0xffffffffu, fo == mvu);
            int mi = rank*32 + (__ffs(mask) - 1);                  // lowest index on ties
            unsigned long long enc = ((unsigned long long)mvu << 8)
                                   | (unsigned long long)(255 - mi);
            if (lane < CL)   // parallel 8-way broadcast, one dest per lane
                st_async_u64_pre(e_rd[bq], e_rm[bq], enc);
            // overlap the logits STG with the enc flight
            logits_out[((size_t)(b*Tn + t))*256 + rank*32 + lane] = logit;
        }

        // per-frame cond reload (write half) overlaps the flights
        if (boundary && tid < 128) sh_cond[tid] = g_cond[(b*Fn + tn1/FSn)*128 + tid];

        // ---------- all warps: next step's W_hh.h(t) during the flights ----------
        mbar_wait(mbH[bq], pc);        // full h(t); early for warps 1-7
        {
            const float* hp = sh_h[bq];
            float a0 = 0.f, a1 = 0.f, a2 = 0.f;
#pragma unroll
            for (int m = 0; m < 32; m++){
                float hv = hp[s + 8*m];            // conflict-free broadcast LDS
                a0 = fmaf(whr[m], hv, a0);
                a1 = fmaf(whz[m], hv, a1);
                a2 = fmaf(whn[m], hv, a2);
            }
#pragma unroll
            for (int off = 4; off >= 1; off >>= 1){
                a0 += __shfl_xor_sync(0xffffffffu, a0, off);
                a1 += __shfl_xor_sync(0xffffffffu, a1, off);
                a2 += __shfl_xor_sync(0xffffffffu, a2, off);
            }
            ghr = a0; ghz = a1; ghn = a2;
        }

        // ---------- global argmax combine, LUT sample, de-emphasis ----------
        mbar_wait(mbE[bq], pc);
        {
            const ulonglong2* ep = reinterpret_cast<const ulonglong2*>(&sh_enc[bq][0]);
            ulonglong2 e0 = ep[0], e1 = ep[1], e2 = ep[2], e3 = ep[3];
            unsigned long long m0 = (e0.x > e0.y) ? e0.x : e0.y;
            unsigned long long m1 = (e1.x > e1.y) ? e1.x : e1.y;
            unsigned long long m2 = (e2.x > e2.y) ? e2.x : e2.y;
            unsigned long long m3 = (e3.x > e3.y) ? e3.x : e3.y;
            m0 = (m1 > m0) ? m1 : m0;
            m2 = (m3 > m2) ? m3 : m2;
            unsigned long long best = (m2 > m0) ? m2 : m0;
            int idx = 255 - (int)(best & 0xFFull);
            prev = sh_mu[idx];
        }
        if (rank == 0 && tid == 0){
            y = prev + 0.97f*y;
            wav_out[b*Tn + t] = y;
        }
        if (boundary){
            __syncthreads();      // cond writes visible before recompute
            calc_consts();
        }
    }
}

// ---------------- launch ----------------
extern "C" void kernel_launch(void* const* d_in, const int* in_sizes, int n_in,
                              void* d_out, int out_size)
{
    const float* features = (const float*)d_in[0];
    const float* c1w = (const float*)d_in[1];
    const float* c1b = (const float*)d_in[2];
    const float* c2w = (const float*)d_in[3];
    const float* c2b = (const float*)d_in[4];
    const float* f1w = (const float*)d_in[5];
    const float* f1b = (const float*)d_in[6];
    const float* f2w = (const float*)d_in[7];
    const float* f2b = (const float*)d_in[8];
    const float* wi  = (const float*)d_in[9];
    const float* wh  = (const float*)d_in[10];
    const float* bi  = (const float*)d_in[11];
    const float* bh  = (const float*)d_in[12];
    const float* oww = (const float*)d_in[13];
    const float* obb = (const float*)d_in[14];

    float* out    = (float*)d_out;
    float* wav    = out;                       // (B, T, 1) flattened first
    float* logits = out + (size_t)Bn*Tn;       // (B, T, 256) after

    frn_conv1<<<Bn*Fn, 128>>>(features, c1w, c1b);
    frn_conv2<<<Bn*Fn, 128>>>(c2w, c2b);
    frn_fc   <<<Bn*Fn, 128>>>(f1w, f1b, f2w, f2b);
    gru_kernel<<<Bn*CL, 256>>>(wi, wh, bi, bh, oww, obb, wav, logits);
}

// round 17
// speedup vs baseline: 1.5853x; 1.0365x over previous
#include <cuda_runtime.h>
#include <cstdint>

#define Bn 8
#define Fn 64
#define Dn 20
#define FSn 160
#define Tn (Fn*FSn)   // 10240
#define CL 8

// ---------------- scratch (device globals; no allocation) ----------------
__device__ float g_c1[Bn*Fn*128];
__device__ float g_c2[Bn*Fn*128];
__device__ float g_cond[Bn*Fn*128];

// ---------------- helpers ----------------
__device__ __forceinline__ uint32_t cl_rank(){
    uint32_t r; asm("mov.u32 %0, %%cluster_ctarank;" : "=r"(r)); return r;
}
__device__ __forceinline__ uint32_t sm2u(const void* p){
    return (uint32_t)__cvta_generic_to_shared(p);
}
__device__ __forceinline__ uint32_t mapa_u32(uint32_t a, uint32_t rnk){
    uint32_t d;
    asm("mapa.shared::cluster.u32 %0, %1, %2;" : "=r"(d) : "r"(a), "r"(rnk));
    return d;
}
__device__ __forceinline__ void cl_arrive(){ asm volatile("barrier.cluster.arrive.aligned;" ::: "memory"); }
__device__ __forceinline__ void cl_wait(){ asm volatile("barrier.cluster.wait.aligned;" ::: "memory"); }

__device__ __forceinline__ void mbar_init(uint32_t mbar, uint32_t cnt){
    asm volatile("mbarrier.init.shared.b64 [%0], %1;" :: "r"(mbar), "r"(cnt) : "memory");
}
__device__ __forceinline__ void mbar_arrive_expect(uint32_t mbar, uint32_t bytes){
    asm volatile("mbarrier.arrive.expect_tx.shared.b64 _, [%0], %1;" :: "r"(mbar), "r"(bytes) : "memory");
}
__device__ __forceinline__ void mbar_wait(uint32_t mbar, uint32_t parity){
    uint32_t done;
    do {
        asm volatile(
            "{\n\t.reg .pred p;\n\t"
            "mbarrier.try_wait.parity.acquire.cta.shared::cta.b64 p, [%1], %2, 0x989680;\n\t"
            "selp.b32 %0, 1, 0, p;\n\t}"
            : "=r"(done) : "r"(mbar), "r"(parity) : "memory");
    } while (!done);
}
// one-sided stores with PRE-MAPPED remote addresses (mapa hoisted out of loop)
__device__ __forceinline__ void st_async_v4_pre(uint32_t rd, uint32_t rm,
                                                float a, float b2, float c, float d){
    asm volatile("st.async.weak.shared::cluster.mbarrier::complete_tx::bytes.v4.b32 "
                 "[%0], {%1,%2,%3,%4}, [%5];"
                 :: "r"(rd), "r"(__float_as_uint(a)), "r"(__float_as_uint(b2)),
                    "r"(__float_as_uint(c)), "r"(__float_as_uint(d)), "r"(rm) : "memory");
}
// plain one-sided relaxed store (tag-in-band exchange; no mbarrier)
__device__ __forceinline__ void st_relaxed_u64_pre(uint32_t rd, unsigned long long v){
    asm volatile("st.relaxed.cluster.shared::cluster.b64 [%0], %1;"
                 :: "r"(rd), "l"(v) : "memory");
}

__device__ __forceinline__ float tanh_approx(float x){
    float y; asm("tanh.approx.f32 %0, %1;" : "=f"(y) : "f"(x)); return y;
}
__device__ __forceinline__ float fsigm_fast(float x){   // sigma(x)=0.5*tanh(x/2)+0.5
    return fmaf(tanh_approx(0.5f*x), 0.5f, 0.5f);
}
__device__ __forceinline__ float ftanh(float x){        // accurate (n-gate)
    x = fminf(fmaxf(x, -10.f), 10.f);
    float e = __expf(2.f*x);
    return (e - 1.f)/(e + 1.f);
}
// monotone float->uint map (larger float => larger uint), finite inputs
__device__ __forceinline__ uint32_t ford(float f){
    uint32_t u = __float_as_uint(f);
    return (u & 0x80000000u) ? ~u : (u | 0x80000000u);
}

// ---------------- FrameRateNet (tiny, 3 kernels) ----------------
__global__ void frn_conv1(const float* __restrict__ feat,
                          const float* __restrict__ w,
                          const float* __restrict__ bias){
    int bf = blockIdx.x; int b = bf >> 6, f = bf & 63;
    int o = threadIdx.x;
    float acc = bias[o];
#pragma unroll
    for (int k = 0; k < 3; k++){
        int ff = f + k - 1;
        if (ff < 0 || ff >= Fn) continue;
        const float* fr = feat + (b*Fn + ff)*Dn;
#pragma unroll
        for (int i = 0; i < Dn; i++) acc += fr[i]*w[(k*Dn + i)*128 + o];
    }
    g_c1[bf*128 + o] = tanhf(acc);
}

__global__ void frn_conv2(const float* __restrict__ w,
                          const float* __restrict__ bias){
    __shared__ float srow[3*128];
    int bf = blockIdx.x; int b = bf >> 6, f = bf & 63;
    int o = threadIdx.x;
#pragma unroll
    for (int k = 0; k < 3; k++){
        int ff = f + k - 1;
        srow[k*128 + o] = (ff >= 0 && ff < Fn) ? g_c1[(b*Fn + ff)*128 + o] : 0.f;
    }
    __syncthreads();
    float acc = bias[o];
#pragma unroll 1
    for (int k = 0; k < 3; k++)
        for (int i = 0; i < 128; i++)
            acc += srow[k*128 + i]*w[(k*128 + i)*128 + o];
    g_c2[bf*128 + o] = tanhf(acc);
}

__global__ void frn_fc(const float* __restrict__ w1, const float* __restrict__ b1,
                       const float* __restrict__ w2, const float* __restrict__ b2){
    __shared__ float sv[128], sm_[128];
    int bf = blockIdx.x; int o = threadIdx.x;
    sv[o] = g_c2[bf*128 + o];
    __syncthreads();
    float a = b1[o];
    for (int j = 0; j < 128; j++) a += sv[j]*w1[j*128 + o];
    sm_[o] = tanhf(a);
    __syncthreads();
    float c = b2[o];
    for (int i = 0; i < 128; i++) c += sm_[i]*w2[i*128 + o];
    g_cond[bf*128 + o] = tanhf(c);
}

// ---------------- persistent autoregressive GRU ----------------
// R12 topology (verified baseline 10.53/10.56 ms). Single isolated delta:
// the E (argmax) exchange uses TAG-IN-BAND relaxed u64 stores + volatile
// spin instead of an mbarrier — removes mbE arm + TRYWAIT from the spine.
// enc = [ford:32][255-idx:8][t & 0xFFFFFF], so max-compare ordering is
// unchanged (tags equal within a step) and stale reads fail the tag check.
__global__ void __launch_bounds__(256, 1) __cluster_dims__(CL, 1, 1)
gru_kernel(const float* __restrict__ wi_g, const float* __restrict__ wh_g,
           const float* __restrict__ bi_g, const float* __restrict__ bh_g,
           const float* __restrict__ ow_g, const float* __restrict__ ob_g,
           float* __restrict__ wav_out, float* __restrict__ logits_out)
{
    __shared__ __align__(16) float sh_h[2][256];      // double-buffered hidden state
    __shared__ __align__(16) float sh_P[2][CL][32];   // partial-logit slices [buf][src][col]
    __shared__ __align__(16) unsigned long long sh_enc[CL];  // tagged enc, single buffer
    __shared__ float sh_cond[128];                    // current-frame conditioning
    __shared__ float sh_mu[256];                      // mu-law idx -> sample LUT
    __shared__ __align__(8) unsigned long long sh_mb[4];  // H0,H1,P0,P1

    const int tid  = threadIdx.x;
    const int rank = (int)cl_rank();
    const int b    = blockIdx.x / CL;
    const int lane = tid & 31;
    const int wid  = tid >> 5;
    const int jl   = wid*4 + (lane >> 3);         // local unit 0..31
    const int s    = lane & 7;                    // k-stripe 0..7
    const int u    = rank*32 + jl;                // global hidden unit

    // ---- recurrent weights into registers ----
    float whr[32], whz[32], whn[32];
#pragma unroll
    for (int m = 0; m < 32; m++){
        int k = s + 8*m;
        whr[m] = wh_g[(u      )*256 + k];
        whz[m] = wh_g[(256 + u)*256 + k];
        whn[m] = wh_g[(512 + u)*256 + k];
    }
    const float wpr = wi_g[(u      )*129];
    const float wpz = wi_g[(256 + u)*129];
    const float wpn = wi_g[(512 + u)*129];
    float wcr[16], wcz[16], wcn[16];
#pragma unroll
    for (int m = 0; m < 16; m++){
        int k = 1 + s + 8*m;
        wcr[m] = wi_g[(u      )*129 + k];
        wcz[m] = wi_g[(256 + u)*129 + k];
        wcn[m] = wi_g[(512 + u)*129 + k];
    }
    // output weights: thread covers its CTA's 32 h-rows for logit column tid
    float ow[32];
#pragma unroll
    for (int j2 = 0; j2 < 32; j2++) ow[j2] = ow_g[(rank*32 + j2)*256 + tid];
    const float ob   = (tid < 32) ? ob_g[rank*32 + tid] : 0.f;
    const float bsr  = bi_g[u]       + bh_g[u];
    const float bsz  = bi_g[256 + u] + bh_g[256 + u];
    const float bin_ = bi_g[512 + u];
    const float bhn  = bh_g[512 + u];

    // ---- init shared state + mbarriers + mu-law LUT ----
    for (int i = tid; i < 2*256; i += 256) ((float*)sh_h)[i] = 0.f;
    if (tid < 128) sh_cond[tid] = g_cond[(b*Fn + 0)*128 + tid];
    if (tid < 4) mbar_init(sm2u(&sh_mb[tid]), 1);
    if (tid < CL) sh_enc[tid] = ~0ull;   // tag 0xFFFFFF != any step tag
    {
        float v  = ((float)tid + 0.5f)*(1.f/128.f) - 1.f;
        float av = fabsf(v);
        sh_mu[tid] = copysignf((exp2f(8.f*av) - 1.f)*(1.f/255.f), v);
    }
    __syncthreads();

    float cr, cz, cn;
    auto calc_consts = [&](){
        float tr = 0.f, tz = 0.f, tn2 = 0.f;
#pragma unroll
        for (int m = 0; m < 16; m++){
            float cv = sh_cond[s + 8*m];
            tr  = fmaf(wcr[m], cv, tr);
            tz  = fmaf(wcz[m], cv, tz);
            tn2 = fmaf(wcn[m], cv, tn2);
        }
#pragma unroll
        for (int off = 4; off >= 1; off >>= 1){
            tr  += __shfl_xor_sync(0xffffffffu, tr,  off);
            tz  += __shfl_xor_sync(0xffffffffu, tz,  off);
            tn2 += __shfl_xor_sync(0xffffffffu, tn2, off);
        }
        cr = tr + bsr; cz = tz + bsz; cn = tn2 + bin_;
    };
    calc_consts();

    cl_arrive(); cl_wait();   // one-time: peers' smem + mbarriers initialized

    const uint32_t mbH[2] = { sm2u(&sh_mb[0]), sm2u(&sh_mb[1]) };
    const uint32_t mbP[2] = { sm2u(&sh_mb[2]), sm2u(&sh_mb[3]) };

    // ---- pre-mapped remote addresses (mapa hoisted out of the loop) ----
    uint32_t h_rd[2], h_rm[2], p_rd[2], p_rm[2];
    uint32_t e_rd;
#pragma unroll
    for (int q = 0; q < 2; q++){
        uint32_t dl = (uint32_t)(lane & 7);
        h_rd[q] = mapa_u32(sm2u(&sh_h[q][rank*32 + wid*4]), dl);
        h_rm[q] = mapa_u32(mbH[q], dl);
        p_rd[q] = mapa_u32(sm2u(&sh_P[q][rank][lane & ~3]), (uint32_t)wid);
        p_rm[q] = mapa_u32(mbP[q], (uint32_t)wid);
    }
    e_rd = mapa_u32(sm2u(&sh_enc[rank]), (uint32_t)(lane & 7));

    volatile unsigned long long* ev = sh_enc;

    float prev = 0.f, hold = 0.f, y = 0.f;
    float ghr = 0.f, ghz = 0.f, ghn = 0.f;   // pipelined, REDUCED W_hh.h partials (h(-1)=0)

    for (int t = 0; t < Tn; ++t){
        const int bq = t & 1;
        const uint32_t pc = (uint32_t)((t >> 1) & 1);

        // arm mbarriers; each armer is in a warp that WAITS that barrier
        if (tid == 0)       mbar_arrive_expect(mbP[bq], 8*8*16);   // pv: 8 srcs x 8 v4
        else if (tid == 32) mbar_arrive_expect(mbH[bq], 7*8*16);   // h: 7 remote x 8 v4

        // ---------- gates tail: W_hh partials were precomputed last step ----------
        float rg   = fsigm_fast(ghr + cr + wpr*prev);
        float zg   = fsigm_fast(ghz + cz + wpz*prev);
        float ng   = ftanh(cn + wpn*prev + rg*(ghn + bhn));
        float hnew = fmaf(zg, hold - ng, ng);     // (1-z)n + z*hold
        hold = hnew;

        // gather this warp's 4 unit values into lanes 0..7 (one per dest CTA)
        float v1 = __shfl_sync(0xffffffffu, hnew, (lane & 7) + 8);
        float v2 = __shfl_sync(0xffffffffu, hnew, (lane & 7) + 16);
        float v3 = __shfl_sync(0xffffffffu, hnew, (lane & 7) + 24);
        if (lane == rank)   // local copy of this warp's slice
            *reinterpret_cast<float4*>(&sh_h[bq][rank*32 + wid*4]) =
                make_float4(hnew, v1, v2, v3);
        __syncthreads();    // local slice complete; anti-WAR before sends
        if (lane < 8 && lane != rank)
            st_async_v4_pre(h_rd[bq], h_rm[bq], hnew, v1, v2, v3);

        // partial logits from LOCAL h slice (2 accumulators)
        float pv0 = 0.f, pv1 = 0.f;
        {
            const float* hq = sh_h[bq] + rank*32;
#pragma unroll
            for (int j2 = 0; j2 < 16; j2++){
                pv0 = fmaf(hq[j2],      ow[j2],      pv0);
                pv1 = fmaf(hq[j2 + 16], ow[j2 + 16], pv1);
            }
        }
        float pv = pv0 + pv1;
        // gather 4 columns into lanes 0 mod 4, one v4 per group to owner CTA
        float q1 = __shfl_sync(0xffffffffu, pv, (lane & ~3) + 1);
        float q2 = __shfl_sync(0xffffffffu, pv, (lane & ~3) + 2);
        float q3 = __shfl_sync(0xffffffffu, pv, (lane & ~3) + 3);
        if ((lane & 3) == 0)
            st_async_v4_pre(p_rd[bq], p_rm[bq], pv, q1, q2, q3);

        int tn1 = t + 1;
        bool boundary = (tn1 < Tn) && ((tn1 % FSn) == 0);

        // ---------- warp 0 ONLY: final logits + argmax + tagged E broadcast ----------
        if (wid == 0){
            mbar_wait(mbP[bq], pc);
            const float* Pp = &sh_P[bq][0][lane];
            float l0 = ob, l1 = 0.f;
#pragma unroll
            for (int src = 0; src < CL; src += 2){
                l0 += Pp[(src    )*32];
                l1 += Pp[(src + 1)*32];
            }
            float logit = l0 + l1;
            uint32_t fo = ford(logit);
            uint32_t mvu = __reduce_max_sync(0xffffffffu, fo);
            uint32_t mask = __ballot_sync(0xffffffffu, fo == mvu);
            int mi = rank*32 + (__ffs(mask) - 1);                  // lowest index on ties
            unsigned long long enc = ((unsigned long long)mvu << 32)
                                   | ((unsigned long long)(255 - mi) << 24)
                                   | (unsigned long long)((uint32_t)t & 0xFFFFFFu);
            if (lane < CL)   // parallel 8-way broadcast, one dest per lane
                st_relaxed_u64_pre(e_rd, enc);
            // overlap the logits STG with the enc flight
            logits_out[((size_t)(b*Tn + t))*256 + rank*32 + lane] = logit;
        }

        // per-frame cond reload (write half) overlaps the flights
        if (boundary && tid < 128) sh_cond[tid] = g_cond[(b*Fn + tn1/FSn)*128 + tid];

        // ---------- all warps: next step's W_hh.h(t) during the flights ----------
        mbar_wait(mbH[bq], pc);        // full h(t); early for warps 1-7
        {
            const float* hp = sh_h[bq];
            float a0 = 0.f, a1 = 0.f, a2 = 0.f;
#pragma unroll
            for (int m = 0; m < 32; m++){
                float hv = hp[s + 8*m];            // conflict-free broadcast LDS
                a0 = fmaf(whr[m], hv, a0);
                a1 = fmaf(whz[m], hv, a1);
                a2 = fmaf(whn[m], hv, a2);
            }
#pragma unroll
            for (int off = 4; off >= 1; off >>= 1){
                a0 += __shfl_xor_sync(0xffffffffu, a0, off);
                a1 += __shfl_xor_sync(0xffffffffu, a1, off);
                a2 += __shfl_xor_sync(0xffffffffu, a2, off);
            }
            ghr = a0; ghz = a1; ghn = a2;
        }

        // ---------- tagged-spin argmax combine, LUT sample, de-emphasis ----------
        {
            const uint32_t want = (uint32_t)t & 0xFFFFFFu;
            unsigned long long best;
            for (;;){
                unsigned long long e0 = ev[0], e1 = ev[1], e2 = ev[2], e3 = ev[3];
                unsigned long long e4 = ev[4], e5 = ev[5], e6 = ev[6], e7 = ev[7];
                uint32_t okc = ((uint32_t)e0 & 0xFFFFFFu) ^ want;
                okc |= ((uint32_t)e1 & 0xFFFFFFu) ^ want;
                okc |= ((uint32_t)e2 & 0xFFFFFFu) ^ want;
                okc |= ((uint32_t)e3 & 0xFFFFFFu) ^ want;
                okc |= ((uint32_t)e4 & 0xFFFFFFu) ^ want;
                okc |= ((uint32_t)e5 & 0xFFFFFFu) ^ want;
                okc |= ((uint32_t)e6 & 0xFFFFFFu) ^ want;
                okc |= ((uint32_t)e7 & 0xFFFFFFu) ^ want;
                if (okc == 0u){
                    unsigned long long m0 = (e0 > e1) ? e0 : e1;
                    unsigned long long m1 = (e2 > e3) ? e2 : e3;
                    unsigned long long m2 = (e4 > e5) ? e4 : e5;
                    unsigned long long m3 = (e6 > e7) ? e6 : e7;
                    m0 = (m1 > m0) ? m1 : m0;
                    m2 = (m3 > m2) ? m3 : m2;
                    best = (m2 > m0) ? m2 : m0;
                    break;
                }
            }
            int idx = 255 - (int)((best >> 24) & 0xFFull);
            prev = sh_mu[idx];
        }
        if (rank == 0 && tid == 0){
            y = prev + 0.97f*y;
            wav_out[b*Tn + t] = y;
        }
        if (boundary){
            __syncthreads();      // cond writes visible before recompute
            calc_consts();
        }
    }
}

// ---------------- launch ----------------
extern "C" void kernel_launch(void* const* d_in, const int* in_sizes, int n_in,
                              void* d_out, int out_size)
{
    const float* features = (const float*)d_in[0];
    const float* c1w = (const float*)d_in[1];
    const float* c1b = (const float*)d_in[2];
    const float* c2w = (const float*)d_in[3];
    const float* c2b = (const float*)d_in[4];
    const float* f1w = (const float*)d_in[5];
    const float* f1b = (const float*)d_in[6];
    const float* f2w = (const float*)d_in[7];
    const float* f2b = (const float*)d_in[8];
    const float* wi  = (const float*)d_in[9];
    const float* wh  = (const float*)d_in[10];
    const float* bi  = (const float*)d_in[11];
    const float* bh  = (const float*)d_in[12];
    const float* oww = (const float*)d_in[13];
    const float* obb = (const float*)d_in[14];

    float* out    = (float*)d_out;
    float* wav    = out;                       // (B, T, 1) flattened first
    float* logits = out + (size_t)Bn*Tn;       // (B, T, 256) after

    frn_conv1<<<Bn*Fn, 128>>>(features, c1w, c1b);
    frn_conv2<<<Bn*Fn, 128>>>(c2w, c2b);
    frn_fc   <<<Bn*Fn, 128>>>(f1w, f1b, f2w, f2b);
    gru_kernel<<<Bn*CL, 256>>>(wi, wh, bi, bh, oww, obb, wav, logits);
}